// round 1
// baseline (speedup 1.0000x reference)
#include <cuda_runtime.h>
#include <math.h>

#define BB   256
#define T2V  1026
#define TP1  1025
#define SSV  1024
#define HHV  32
#define ENV  32
#define NVOC 35
#define H7   224
#define EPSV 2.220446049250313e-16f

// ---------------- device scratch (static, allocation-free) ----------------
static __device__ float g_prex[NVOC * H7];
static __device__ float g_c [BB * TP1 * HHV];
static __device__ float g_cb[BB * TP1 * HHV];
static __device__ float g_d [BB * TP1 * HHV];
static __device__ float g_o [BB * TP1 * HHV];
static __device__ float g_h [BB * TP1 * HHV];
static __device__ float g_loglam[BB];
static __device__ float g_nev[BB];
static __device__ float g_integ[BB];

// ---------------- helpers ----------------
__device__ __forceinline__ float softplus_f(float x) {
    return fmaxf(x, 0.0f) + log1pf(expf(-fabsf(x)));
}
__device__ __forceinline__ float sigmoid_f(float x) {
    return 1.0f / (1.0f + expf(-x));
}

// block reduction (result valid on thread 0)
__device__ __forceinline__ float block_reduce(float v, float* sh) {
    #pragma unroll
    for (int o = 16; o > 0; o >>= 1) v += __shfl_down_sync(0xffffffffu, v, o);
    int wid = threadIdx.x >> 5, lid = threadIdx.x & 31;
    if (lid == 0) sh[wid] = v;
    __syncthreads();
    if (wid == 0) {
        v = (lid < 8) ? sh[lid] : 0.0f;
        #pragma unroll
        for (int o = 4; o > 0; o >>= 1) v += __shfl_down_sync(0xffffffffu, v, o);
    }
    return v;
}

// ---------------- kernel A: precompute prex[v][j] = Emb[v]·Wx[:,j] + b[j] ---
__global__ void k_prex(const float* __restrict__ Emb,
                       const float* __restrict__ W,
                       const float* __restrict__ bias) {
    int v = blockIdx.x;
    int j = threadIdx.x;              // 224 threads
    float acc = bias[j];
    #pragma unroll
    for (int k = 0; k < 32; k++)
        acc += Emb[v * 32 + k] * W[k * H7 + j];
    g_prex[v * H7 + j] = acc;
}

// ---------------- kernel B: sequential CTLSTM scan, one CTA per batch ------
__global__ void __launch_bounds__(256, 2)
k_scan(const int* __restrict__ event,
       const float* __restrict__ dtime,
       const float* __restrict__ W) {
    const int b = blockIdx.x;
    const int j = threadIdx.x;

    __shared__ float h_sh[32];
    __shared__ float act[H7];

    // each thread j<224 owns the j-th column of W_h (rows 32..63 of W)
    float wcol[32];
    if (j < H7) {
        #pragma unroll
        for (int k = 0; k < 32; k++)
            wcol[k] = W[(32 + k) * H7 + j];
    }
    if (j < 32) h_sh[j] = 0.0f;

    float cm = 0.0f, cbm = 0.0f;   // carry (only meaningful for j<32)
    const int*   evrow = event + b * T2V;
    const float* dtrow = dtime + b * T2V;
    __syncthreads();

    for (int t = 0; t < TP1; t++) {
        if (j < H7) {
            int ev = evrow[t];
            float pre = g_prex[ev * H7 + j];
            #pragma unroll
            for (int k = 0; k < 32; k++)
                pre = fmaf(h_sh[k], wcol[k], pre);
            int gi = j >> 5;
            float a;
            if (gi == 2)      a = tanhf(pre);          // z
            else if (gi == 6) a = softplus_f(pre);     // delta
            else              a = sigmoid_f(pre);      // i,f,o,ib,fb
            act[j] = a;
        }
        __syncthreads();
        if (j < 32) {
            float iv  = act[j];
            float fv  = act[32  + j];
            float zv  = act[64  + j];
            float ov  = act[96  + j];
            float ibv = act[128 + j];
            float fbv = act[160 + j];
            float dl  = act[192 + j];

            float c  = fv * cm + iv * zv;
            float cb = fbv * cbm + ibv * zv;
            float dt = dtrow[t + 1];
            float e  = expf(-dl * dt);
            float cn = cb + (c - cb) * e;
            float h  = ov * tanhf(cn);

            int base = (b * TP1 + t) * 32 + j;
            g_c [base] = c;
            g_cb[base] = cb;
            g_d [base] = dl;
            g_o [base] = ov;
            g_h [base] = h;

            h_sh[j] = h;
            cm = cn; cbm = cb;
        }
        __syncthreads();
    }
}

// ---------------- kernel C: MC sampling + lambda_sample + integral ---------
__global__ void __launch_bounds__(256)
k_sample(const float* __restrict__ dts,
         const float* __restrict__ mask,
         const float* __restrict__ dur,
         const float* __restrict__ Wl,
         float* __restrict__ lam_out) {
    const int b   = blockIdx.x;
    const int tid = threadIdx.x;

    __shared__ float wl[32 * 32];
    __shared__ float red[8];
    for (int i = tid; i < 1024; i += 256) wl[i] = Wl[i];
    __syncthreads();

    float accLam = 0.0f, accMask = 0.0f;

    for (int s = tid; s < SSV; s += 256) {
        int r  = b * SSV + s;                 // flat row (also output row index)
        int bs = r / TP1;
        int ts = r - bs * TP1;
        int base = (bs * TP1 + ts) * 32;
        float dtv = dts[r];

        float ch[32];
        const float4* c4  = (const float4*)(g_c  + base);
        const float4* cb4 = (const float4*)(g_cb + base);
        const float4* d4  = (const float4*)(g_d  + base);
        const float4* o4  = (const float4*)(g_o  + base);
        #pragma unroll
        for (int q = 0; q < 8; q++) {
            float4 cv  = c4[q];
            float4 cbv = cb4[q];
            float4 dv  = d4[q];
            float4 ov  = o4[q];
            float cd;
            cd = cbv.x + (cv.x - cbv.x) * expf(-dv.x * dtv); ch[q*4+0] = ov.x * tanhf(cd);
            cd = cbv.y + (cv.y - cbv.y) * expf(-dv.y * dtv); ch[q*4+1] = ov.y * tanhf(cd);
            cd = cbv.z + (cv.z - cbv.z) * expf(-dv.z * dtv); ch[q*4+2] = ov.z * tanhf(cd);
            cd = cbv.w + (cv.w - cbv.w) * expf(-dv.w * dtv); ch[q*4+3] = ov.w * tanhf(cd);
        }

        float lamsum = 0.0f;
        float* outrow = lam_out + (size_t)r * 32;
        #pragma unroll 4
        for (int e = 0; e < 32; e++) {
            float acc = 0.0f;
            #pragma unroll
            for (int k = 0; k < 32; k++)
                acc = fmaf(ch[k], wl[e * 32 + k], acc);
            float sp = softplus_f(acc);
            outrow[e] = sp;
            lamsum += sp;
        }
        float m = mask[r];
        accLam  += lamsum * m;
        accMask += m;
    }

    float sLam = block_reduce(accLam, red);
    __syncthreads();
    float sMask = block_reduce(accMask, red);
    if (tid == 0) g_integ[b] = (sLam / sMask) * dur[b];
}

// ---------------- kernel D: target log-lambda sum + event count ------------
__global__ void __launch_bounds__(256)
k_target(const int* __restrict__ event,
         const float* __restrict__ Wl) {
    const int b   = blockIdx.x;
    const int tid = threadIdx.x;

    __shared__ float wl[32 * 32];
    __shared__ float red[8];
    for (int i = tid; i < 1024; i += 256) wl[i] = Wl[i];
    __syncthreads();

    float accL = 0.0f, accN = 0.0f;
    for (int t = tid; t < TP1; t += 256) {
        int tgt = event[b * T2V + t + 1];
        bool m  = (tgt < ENV);
        int tt  = m ? tgt : 0;
        const float* hrow = g_h + (b * TP1 + t) * 32;
        float acc = 0.0f;
        #pragma unroll
        for (int k = 0; k < 32; k++)
            acc = fmaf(hrow[k], wl[tt * 32 + k], acc);
        float lam = softplus_f(acc);
        if (m) { accL += logf(lam + EPSV); accN += 1.0f; }
    }

    float sL = block_reduce(accL, red);
    __syncthreads();
    float sN = block_reduce(accN, red);
    if (tid == 0) { g_loglam[b] = sL; g_nev[b] = sN; }
}

// ---------------- kernel E: final scalars -----------------------------------
__global__ void __launch_bounds__(256)
k_final(float* __restrict__ out) {
    const int tid = threadIdx.x;     // one thread per batch element
    __shared__ float red[8];
    float lp = g_loglam[tid] - g_integ[tid];
    float nv = g_nev[tid];
    float sLP = block_reduce(lp, red);
    __syncthreads();
    float sNV = block_reduce(nv, red);
    if (tid == 0) {
        out[0] = -sLP;
        out[1] = sNV;
    }
}

// ---------------- launch ----------------
extern "C" void kernel_launch(void* const* d_in, const int* in_sizes, int n_in,
                              void* d_out, int out_size) {
    const int*   event = (const int*)  d_in[0];
    const float* dtime = (const float*)d_in[1];
    const float* dur   = (const float*)d_in[2];
    const float* dts   = (const float*)d_in[3];
    // d_in[4] = index_of_hidden_sampling (unused by the reference)
    const float* mask  = (const float*)d_in[5];
    const float* Emb   = (const float*)d_in[6];
    const float* W     = (const float*)d_in[7];
    const float* bias  = (const float*)d_in[8];
    const float* Wl    = (const float*)d_in[9];

    float* out = (float*)d_out;
    // lambda_sample occupies the tail of the output buffer; scalars lead.
    long long lam_elems = (long long)BB * SSV * ENV;
    long long lamoff = (long long)out_size - lam_elems;
    if (lamoff < 0) lamoff = 0;
    float* lam_out = out + lamoff;

    k_prex  <<<NVOC, H7>>>(Emb, W, bias);
    k_scan  <<<BB, 256>>>(event, dtime, W);
    k_sample<<<BB, 256>>>(dts, mask, dur, Wl, lam_out);
    k_target<<<BB, 256>>>(event, Wl);
    k_final <<<1, 256>>>(out);
}

// round 2
// speedup vs baseline: 1.0550x; 1.0550x over previous
#include <cuda_runtime.h>
#include <math.h>

#define BB   256
#define T2V  1026
#define TP1  1025
#define SSV  1024
#define HHV  32
#define ENV  32
#define NVOC 35
#define H7   224
#define EPSV 2.220446049250313e-16f

// ---------------- device scratch (static, allocation-free) ----------------
static __device__ float g_prex[NVOC * H7];
static __device__ float g_c [BB * TP1 * HHV];
static __device__ float g_cb[BB * TP1 * HHV];
static __device__ float g_d [BB * TP1 * HHV];
static __device__ float g_o [BB * TP1 * HHV];
static __device__ float g_h [BB * TP1 * HHV];
static __device__ float g_loglam[BB];
static __device__ float g_nev[BB];
static __device__ float g_integ[BB];

// ---------------- fast-math helpers (MUFU based, ~1e-6 rel err) ----------
__device__ __forceinline__ float sig_fast(float x) {
    return __fdividef(1.0f, 1.0f + __expf(-x));
}
__device__ __forceinline__ float tanh_fast(float x) {
    return fmaf(2.0f, __fdividef(1.0f, 1.0f + __expf(-2.0f * x)), -1.0f);
}
__device__ __forceinline__ float softplus_fast(float x) {
    return fmaxf(x, 0.0f) + __logf(1.0f + __expf(-fabsf(x)));
}

// block reduction (result valid on thread 0); blockDim = 256
__device__ __forceinline__ float block_reduce(float v, float* sh) {
    #pragma unroll
    for (int o = 16; o > 0; o >>= 1) v += __shfl_down_sync(0xffffffffu, v, o);
    int wid = threadIdx.x >> 5, lid = threadIdx.x & 31;
    if (lid == 0) sh[wid] = v;
    __syncthreads();
    if (wid == 0) {
        v = (lid < 8) ? sh[lid] : 0.0f;
        #pragma unroll
        for (int o = 4; o > 0; o >>= 1) v += __shfl_down_sync(0xffffffffu, v, o);
    }
    return v;
}

// ---------------- kernel A: prex[v][j] = Emb[v]·Wx[:,j] + b[j] ------------
__global__ void k_prex(const float* __restrict__ Emb,
                       const float* __restrict__ W,
                       const float* __restrict__ bias) {
    int v = blockIdx.x;
    int j = threadIdx.x;              // 224 threads
    float acc = bias[j];
    #pragma unroll
    for (int k = 0; k < 32; k++)
        acc += Emb[v * 32 + k] * W[k * H7 + j];
    g_prex[v * H7 + j] = acc;
}

// ---------------- kernel B: sequential CTLSTM scan, one CTA per batch ------
__global__ void __launch_bounds__(224, 2)
k_scan(const int* __restrict__ event,
       const float* __restrict__ dtime,
       const float* __restrict__ W) {
    const int b = blockIdx.x;
    const int j = threadIdx.x;
    const int gi = j >> 5;

    __shared__ float4 h4[8];
    __shared__ float act[H7];
    __shared__ float prex_sh[NVOC * H7];
    float* h_sh = (float*)h4;

    // stage prex table into SMEM (conflict-free per-step reads)
    for (int i = j; i < NVOC * H7; i += H7) prex_sh[i] = g_prex[i];

    // thread j owns the j-th column of W_h (rows 32..63 of W)
    float wcol[32];
    #pragma unroll
    for (int k = 0; k < 32; k++)
        wcol[k] = W[(32 + k) * H7 + j];

    if (j < 32) h_sh[j] = 0.0f;

    float cm = 0.0f, cbm = 0.0f;
    const int*   evrow = event + b * T2V;
    const float* dtrow = dtime + b * T2V;

    int   ev      = evrow[0];
    float dt_next = dtrow[1];

    float* outc  = g_c  + b * TP1 * 32;
    float* outcb = g_cb + b * TP1 * 32;
    float* outd  = g_d  + b * TP1 * 32;
    float* outo  = g_o  + b * TP1 * 32;
    float* outh  = g_h  + b * TP1 * 32;

    __syncthreads();

    for (int t = 0; t < TP1; t++) {
        // phase 1: pre = prex[ev] + h·W_h, then gate activation
        float pre = prex_sh[ev * H7 + j];
        float a0 = 0.f, a1 = 0.f, a2 = 0.f, a3 = 0.f;
        #pragma unroll
        for (int q = 0; q < 8; q++) {
            float4 hv = h4[q];
            a0 = fmaf(hv.x, wcol[4 * q + 0], a0);
            a1 = fmaf(hv.y, wcol[4 * q + 1], a1);
            a2 = fmaf(hv.z, wcol[4 * q + 2], a2);
            a3 = fmaf(hv.w, wcol[4 * q + 3], a3);
        }
        pre += (a0 + a1) + (a2 + a3);

        float a;
        if (gi == 2)      a = tanh_fast(pre);       // z
        else if (gi == 6) a = softplus_fast(pre);   // delta
        else              a = sig_fast(pre);        // i,f,o,ib,fb
        act[j] = a;

        // offloaded stores (not on warp-0 critical path)
        if (gi == 3) outo[t * 32 + (j - 96)]  = a;  // o gate
        if (gi == 6) outd[t * 32 + (j - 192)] = a;  // delta

        // prefetch next event token while others finish
        if (t + 1 < TP1) ev = evrow[t + 1];

        __syncthreads();

        // phase 2: cell update + decay (warp 0 only)
        if (j < 32) {
            float iv  = act[j];
            float fv  = act[32  + j];
            float zv  = act[64  + j];
            float ov  = act[96  + j];
            float ibv = act[128 + j];
            float fbv = act[160 + j];
            float dl  = act[192 + j];

            float c  = fmaf(fv, cm, iv * zv);
            float cb = fmaf(fbv, cbm, ibv * zv);
            float e  = __expf(-dl * dt_next);
            float cn = fmaf(c - cb, e, cb);
            float h  = ov * tanh_fast(cn);

            int base = t * 32 + j;
            outc [base] = c;
            outcb[base] = cb;
            outh [base] = h;

            h_sh[j] = h;
            cm = cn; cbm = cb;
            if (t + 1 < TP1) dt_next = dtrow[t + 2];
        }
        __syncthreads();
    }
}

// ---------------- kernel C: MC sampling + lambda_sample + integral ---------
// warp-per-row: coalesced loads, ch staged in SMEM (broadcast reads),
// Wl row in registers per lane, coalesced output.
__global__ void __launch_bounds__(256)
k_sample(const float* __restrict__ dts,
         const float* __restrict__ mask,
         const float* __restrict__ dur,
         const float* __restrict__ Wl,
         float* __restrict__ lam_out) {
    const int b    = blockIdx.x;
    const int tid  = threadIdx.x;
    const int lane = tid & 31;
    const int wid  = tid >> 5;

    __shared__ float sh_ch[8][32];
    __shared__ float red[8];

    // lane e keeps Wl[e][0..31] in registers
    float wle[32];
    const float4* wl4 = (const float4*)(Wl + lane * 32);
    #pragma unroll
    for (int q = 0; q < 8; q++) {
        float4 w = wl4[q];
        wle[4 * q + 0] = w.x; wle[4 * q + 1] = w.y;
        wle[4 * q + 2] = w.z; wle[4 * q + 3] = w.w;
    }

    float accLam = 0.0f, accMask = 0.0f;

    for (int s = wid; s < SSV; s += 8) {
        int r    = b * SSV + s;          // == flat hidden row index
        int base = r * 32;

        float cv  = g_c [base + lane];
        float cbv = g_cb[base + lane];
        float dv  = g_d [base + lane];
        float ov  = g_o [base + lane];
        float dtv = dts[r];

        float cd  = fmaf(cv - cbv, __expf(-dv * dtv), cbv);
        float chv = ov * tanh_fast(cd);
        sh_ch[wid][lane] = chv;
        __syncwarp();

        float d0 = 0.f, d1 = 0.f, d2 = 0.f, d3 = 0.f;
        const float4* ch4 = (const float4*)sh_ch[wid];
        #pragma unroll
        for (int q = 0; q < 8; q++) {
            float4 c4 = ch4[q];      // broadcast, conflict-free
            d0 = fmaf(c4.x, wle[4 * q + 0], d0);
            d1 = fmaf(c4.y, wle[4 * q + 1], d1);
            d2 = fmaf(c4.z, wle[4 * q + 2], d2);
            d3 = fmaf(c4.w, wle[4 * q + 3], d3);
        }
        float sp = softplus_fast((d0 + d1) + (d2 + d3));
        lam_out[(size_t)r * 32 + lane] = sp;

        float m = mask[r];
        accLam += sp * m;
        if (lane == 0) accMask += m;
        __syncwarp();
    }

    float sLam = block_reduce(accLam, red);
    __syncthreads();
    float sMask = block_reduce(accMask, red);
    if (tid == 0) g_integ[b] = __fdividef(sLam, sMask) * dur[b];
}

// ---------------- kernel D: target log-lambda sum + event count ------------
// warp-per-row: coalesced g_h reads, conflict-free wl reads, shfl reduce.
__global__ void __launch_bounds__(256)
k_target(const int* __restrict__ event,
         const float* __restrict__ Wl) {
    const int b    = blockIdx.x;
    const int tid  = threadIdx.x;
    const int lane = tid & 31;
    const int wid  = tid >> 5;

    __shared__ float wl[32 * 32];
    __shared__ float red[8];
    for (int i = tid; i < 1024; i += 256) wl[i] = Wl[i];
    __syncthreads();

    const int* evrow = event + b * T2V;
    float accL = 0.0f, accN = 0.0f;

    for (int t = wid; t < TP1; t += 8) {
        int tgt = evrow[t + 1];
        bool m  = (tgt < ENV);
        int tt  = m ? tgt : 0;

        float hv = g_h[(b * TP1 + t) * 32 + lane];  // coalesced
        float p  = hv * wl[tt * 32 + lane];          // bank = lane, no conflict
        #pragma unroll
        for (int o = 16; o > 0; o >>= 1) p += __shfl_down_sync(0xffffffffu, p, o);

        if (lane == 0 && m) {
            accL += __logf(softplus_fast(p) + EPSV);
            accN += 1.0f;
        }
    }

    float sL = block_reduce(accL, red);
    __syncthreads();
    float sN = block_reduce(accN, red);
    if (tid == 0) { g_loglam[b] = sL; g_nev[b] = sN; }
}

// ---------------- kernel E: final scalars -----------------------------------
__global__ void __launch_bounds__(256)
k_final(float* __restrict__ out) {
    const int tid = threadIdx.x;     // one thread per batch element
    __shared__ float red[8];
    float lp = g_loglam[tid] - g_integ[tid];
    float nv = g_nev[tid];
    float sLP = block_reduce(lp, red);
    __syncthreads();
    float sNV = block_reduce(nv, red);
    if (tid == 0) {
        out[0] = -sLP;
        out[1] = sNV;
    }
}

// ---------------- launch ----------------
extern "C" void kernel_launch(void* const* d_in, const int* in_sizes, int n_in,
                              void* d_out, int out_size) {
    const int*   event = (const int*)  d_in[0];
    const float* dtime = (const float*)d_in[1];
    const float* dur   = (const float*)d_in[2];
    const float* dts   = (const float*)d_in[3];
    // d_in[4] = index_of_hidden_sampling (unused by the reference)
    const float* mask  = (const float*)d_in[5];
    const float* Emb   = (const float*)d_in[6];
    const float* W     = (const float*)d_in[7];
    const float* bias  = (const float*)d_in[8];
    const float* Wl    = (const float*)d_in[9];

    float* out = (float*)d_out;
    long long lam_elems = (long long)BB * SSV * ENV;
    long long lamoff = (long long)out_size - lam_elems;
    if (lamoff < 0) lamoff = 0;
    float* lam_out = out + lamoff;

    k_prex  <<<NVOC, H7>>>(Emb, W, bias);
    k_scan  <<<BB, H7>>>(event, dtime, W);
    k_sample<<<BB, 256>>>(dts, mask, dur, Wl, lam_out);
    k_target<<<BB, 256>>>(event, Wl);
    k_final <<<1, 256>>>(out);
}